// round 1
// baseline (speedup 1.0000x reference)
#include <cuda_runtime.h>

// GraphAttentionLayer: B=8, T=2048, Din=Dout=256
//   h  = x @ W^T                         (16384 x 256 x 256 GEMM)
//   s1 = h @ a[:256], s2 = h @ a[256:]
//   w(i,j) = exp(lrelu(s1_i + s2_j))     (no max-subtraction needed: |e| <= ~8)
//   out[b,i,:] = elu( (sum_j w h[b,j,:]) / (sum_j w) )
//
// Pipeline: K1 h-GEMM -> K2 s-vectors -> K5 attention GEMM with on-the-fly
// weights + fused denominator + ELU epilogue. All fp32, packed fma.rn.f32x2.

#define B_ 8
#define T_ 2048
#define D_ 256
#define BT_ (B_ * T_)
#define NEG_SLOPE 0.2f

typedef unsigned long long ull;

// Scratch (device globals: allocation-free per harness rules)
__device__ float g_h[BT_ * D_];    // 16 MB
__device__ float g_s1[BT_];
__device__ float g_s2[BT_];

// ---- packed f32x2 helpers (Blackwell sm_100+) ----
__device__ __forceinline__ ull pk(float x, float y) {
  ull r; asm("mov.b64 %0, {%1, %2};" : "=l"(r) : "f"(x), "f"(y)); return r;
}
__device__ __forceinline__ void upk(ull v, float &x, float &y) {
  asm("mov.b64 {%0, %1}, %2;" : "=f"(x), "=f"(y) : "l"(v));
}
__device__ __forceinline__ void fma2(ull &d, ull a, ull b) {
  asm("fma.rn.f32x2 %0, %1, %2, %0;" : "+l"(d) : "l"(a), "l"(b));
}

// ============================================================================
// K1: h = x @ W^T.  M=16384, N=256, K=256. Tiles 128x128x16, 256 threads,
// 8x8 per thread, f32x2 accumulators.
// ============================================================================
__global__ __launch_bounds__(256) void k_gemm_h(
    const float* __restrict__ x, const float* __restrict__ W) {
  __shared__ float As[16][128];
  __shared__ float Bs[16][128];
  const int t  = threadIdx.x;
  const int tx = t & 15, ty = t >> 4;
  const int i0 = blockIdx.y * 128;
  const int o0 = blockIdx.x * 128;

  ull c2[8][4];
#pragma unroll
  for (int r = 0; r < 8; r++)
#pragma unroll
    for (int j = 0; j < 4; j++) c2[r][j] = 0ull;

  for (int k0 = 0; k0 < 256; k0 += 16) {
#pragma unroll
    for (int p = 0; p < 2; p++) {
      int v  = t + p * 256;
      int m  = v >> 2;
      int kq = (v & 3) << 2;
      float4 fa = *(const float4*)&x[(size_t)(i0 + m) * 256 + k0 + kq];
      As[kq + 0][m] = fa.x; As[kq + 1][m] = fa.y;
      As[kq + 2][m] = fa.z; As[kq + 3][m] = fa.w;
      float4 fb = *(const float4*)&W[(size_t)(o0 + m) * 256 + k0 + kq];
      Bs[kq + 0][m] = fb.x; Bs[kq + 1][m] = fb.y;
      Bs[kq + 2][m] = fb.z; Bs[kq + 3][m] = fb.w;
    }
    __syncthreads();
#pragma unroll
    for (int k = 0; k < 16; k++) {
      float4 a0 = *(const float4*)&As[k][ty * 8];
      float4 a1 = *(const float4*)&As[k][ty * 8 + 4];
      ull bb[4];
#pragma unroll
      for (int j = 0; j < 4; j++)
        bb[j] = *(const ull*)&Bs[k][tx * 8 + j * 2];
      float ar[8] = {a0.x, a0.y, a0.z, a0.w, a1.x, a1.y, a1.z, a1.w};
#pragma unroll
      for (int r = 0; r < 8; r++) {
        ull ap = pk(ar[r], ar[r]);
#pragma unroll
        for (int j = 0; j < 4; j++) fma2(c2[r][j], ap, bb[j]);
      }
    }
    __syncthreads();
  }

#pragma unroll
  for (int r = 0; r < 8; r++) {
    float e[8];
#pragma unroll
    for (int j = 0; j < 4; j++) upk(c2[r][j], e[2 * j], e[2 * j + 1]);
    size_t base = (size_t)(i0 + ty * 8 + r) * 256 + o0 + tx * 8;
    *(float4*)&g_h[base]     = make_float4(e[0], e[1], e[2], e[3]);
    *(float4*)&g_h[base + 4] = make_float4(e[4], e[5], e[6], e[7]);
  }
}

// ============================================================================
// K2: s1[row] = h[row,:] . a[:256],  s2[row] = h[row,:] . a[256:]
// One warp per row, 8 rows per block.
// ============================================================================
__global__ __launch_bounds__(256) void k_sv(const float* __restrict__ a) {
  __shared__ float a_s[512];
  const int t = threadIdx.x;
  a_s[t]       = a[t];
  a_s[t + 256] = a[t + 256];
  __syncthreads();
  const int warp = t >> 5, lane = t & 31;
  const int row = blockIdx.x * 8 + warp;
  const float* hr = &g_h[(size_t)row * 256];
  float s1 = 0.f, s2 = 0.f;
#pragma unroll
  for (int c = 0; c < 256; c += 32) {
    float hv = hr[c + lane];
    s1 += hv * a_s[c + lane];
    s2 += hv * a_s[256 + c + lane];
  }
#pragma unroll
  for (int o = 16; o > 0; o >>= 1) {
    s1 += __shfl_xor_sync(0xffffffffu, s1, o);
    s2 += __shfl_xor_sync(0xffffffffu, s2, o);
  }
  if (lane == 0) { g_s1[row] = s1; g_s2[row] = s2; }
}

// ============================================================================
// K5: per-batch attention GEMM out[i,o] = elu( (sum_j w(i,j) h[j,o]) / den_i )
// M=2048 (i), N=256 (o), K=2048 (j). Tiles 128x128x16. Weight tile computed
// on the fly from s1/s2 (smem-resident); denominator accumulated from the
// w-tile; division + ELU fused into the epilogue.
// ============================================================================
__global__ __launch_bounds__(256) void k_attn(float* __restrict__ out) {
  __shared__ float Ws[16][128];   // attention-weight tile (A operand)
  __shared__ float Hs[16][128];   // h tile (B operand)
  __shared__ float s2s[2048];
  __shared__ float s1s[128];
  __shared__ float dens[128];

  const int t  = threadIdx.x;
  const int tx = t & 15, ty = t >> 4;
  const int b  = blockIdx.z;
  const int i0 = blockIdx.y * 128;
  const int o0 = blockIdx.x * 128;
  const float* hb = &g_h[(size_t)b * T_ * 256];

  if (t < 128) { s1s[t] = g_s1[b * T_ + i0 + t]; dens[t] = 0.f; }
#pragma unroll
  for (int j = t; j < 2048; j += 256) s2s[j] = g_s2[b * T_ + j];
  __syncthreads();

  ull c2[8][4];
#pragma unroll
  for (int r = 0; r < 8; r++)
#pragma unroll
    for (int j = 0; j < 4; j++) c2[r][j] = 0ull;

  const int wk  = t >> 4;          // k-row of w tile this thread fills
  const int wm0 = (t & 15) * 8;    // 8 consecutive i-rows

  for (int j0 = 0; j0 < 2048; j0 += 16) {
    // load h tile [16 x 128]
#pragma unroll
    for (int p = 0; p < 2; p++) {
      int v = t + p * 256;
      int k = v >> 5;
      int n = (v & 31) << 2;
      *(float4*)&Hs[k][n] =
          *(const float4*)&hb[(size_t)(j0 + k) * 256 + o0 + n];
    }
    // generate w tile [16 x 128]
    {
      float s2v = s2s[j0 + wk];
      float w[8];
#pragma unroll
      for (int q = 0; q < 8; q++) {
        float e = s1s[wm0 + q] + s2v;
        e = e > 0.f ? e : NEG_SLOPE * e;
        w[q] = __expf(e);
      }
      *(float4*)&Ws[wk][wm0]     = make_float4(w[0], w[1], w[2], w[3]);
      *(float4*)&Ws[wk][wm0 + 4] = make_float4(w[4], w[5], w[6], w[7]);
    }
    __syncthreads();

    // denominator: per-row sum of this w tile
    if (t < 128) {
      float acc = 0.f;
#pragma unroll
      for (int k = 0; k < 16; k++) acc += Ws[k][t];
      dens[t] += acc;
    }

    // main FMA loop
#pragma unroll
    for (int k = 0; k < 16; k++) {
      float4 a0 = *(const float4*)&Ws[k][ty * 8];
      float4 a1 = *(const float4*)&Ws[k][ty * 8 + 4];
      ull bb[4];
#pragma unroll
      for (int j = 0; j < 4; j++)
        bb[j] = *(const ull*)&Hs[k][tx * 8 + j * 2];
      float ar[8] = {a0.x, a0.y, a0.z, a0.w, a1.x, a1.y, a1.z, a1.w};
#pragma unroll
      for (int r = 0; r < 8; r++) {
        ull ap = pk(ar[r], ar[r]);
#pragma unroll
        for (int j = 0; j < 4; j++) fma2(c2[r][j], ap, bb[j]);
      }
    }
    __syncthreads();
  }

  // epilogue: divide by denominator, ELU, store
  float* ob = out + (size_t)b * T_ * 256;
#pragma unroll
  for (int r = 0; r < 8; r++) {
    int m = ty * 8 + r;
    float inv = 1.0f / dens[m];
    float e[8];
#pragma unroll
    for (int j = 0; j < 4; j++) upk(c2[r][j], e[2 * j], e[2 * j + 1]);
#pragma unroll
    for (int q = 0; q < 8; q++) {
      float v = e[q] * inv;
      e[q] = v > 0.f ? v : expm1f(v);   // elu, alpha=1
    }
    size_t base = (size_t)(i0 + m) * 256 + o0 + tx * 8;
    *(float4*)&ob[base]     = make_float4(e[0], e[1], e[2], e[3]);
    *(float4*)&ob[base + 4] = make_float4(e[4], e[5], e[6], e[7]);
  }
}

// ============================================================================
extern "C" void kernel_launch(void* const* d_in, const int* in_sizes, int n_in,
                              void* d_out, int out_size) {
  (void)in_sizes; (void)n_in; (void)out_size;
  const float* x = (const float*)d_in[0];
  const float* W = (const float*)d_in[1];
  const float* a = (const float*)d_in[2];
  float* out = (float*)d_out;

  dim3 g1(2, 128);          // N-tiles x M-tiles
  k_gemm_h<<<g1, 256>>>(x, W);

  k_sv<<<BT_ / 8, 256>>>(a);

  dim3 g3(2, 16, 8);        // o-tiles x i-tiles x batch
  k_attn<<<g3, 256>>>(out);
}

// round 3
// speedup vs baseline: 2.6450x; 2.6450x over previous
#include <cuda_runtime.h>
#include <cuda_bf16.h>
#include <cstdint>

// GraphAttentionLayer B=8,T=2048,D=256 — mma.sync bf16 pipeline (compute_100-safe).
//  K1: h = x@W^T, split-3 bf16 mma; epilogue: s1/s2 + h hi/lo stores
//  K2: out = elu( (W_att @ h) / den ), w on the fly (bf16), h split-2

#define B_ 8
#define T_ 2048
#define NEG_SLOPE 0.2f

__device__ __nv_bfloat16 g_h_hi[B_ * T_ * 256];   // [b][j][o]
__device__ __nv_bfloat16 g_h_lo[B_ * T_ * 256];
__device__ float g_s1[B_ * T_];
__device__ float g_s2[B_ * T_];

// ---------------- helpers ----------------------------------------------------
__device__ __forceinline__ uint32_t smem_u32(const void* p) {
  uint32_t a;
  asm("{ .reg .u64 t; cvta.to.shared.u64 t, %1; cvt.u32.u64 %0, t; }"
      : "=r"(a) : "l"(p));
  return a;
}
__device__ __forceinline__ void ldsm4(uint32_t addr, uint32_t r[4]) {
  asm volatile("ldmatrix.sync.aligned.m8n8.x4.shared.b16 {%0,%1,%2,%3}, [%4];"
               : "=r"(r[0]), "=r"(r[1]), "=r"(r[2]), "=r"(r[3]) : "r"(addr));
}
__device__ __forceinline__ void ldsm4t(uint32_t addr, uint32_t r[4]) {
  asm volatile("ldmatrix.sync.aligned.m8n8.x4.trans.shared.b16 {%0,%1,%2,%3}, [%4];"
               : "=r"(r[0]), "=r"(r[1]), "=r"(r[2]), "=r"(r[3]) : "r"(addr));
}
__device__ __forceinline__ void mma16816(float c[4], const uint32_t a[4],
                                         uint32_t b0, uint32_t b1) {
  asm volatile(
      "mma.sync.aligned.m16n8k16.row.col.f32.bf16.bf16.f32 "
      "{%0,%1,%2,%3}, {%4,%5,%6,%7}, {%8,%9}, {%0,%1,%2,%3};"
      : "+f"(c[0]), "+f"(c[1]), "+f"(c[2]), "+f"(c[3])
      : "r"(a[0]), "r"(a[1]), "r"(a[2]), "r"(a[3]), "r"(b0), "r"(b1));
}
__device__ __forceinline__ void cpa16(uint32_t dst, const void* src) {
  asm volatile("cp.async.cg.shared.global [%0], [%1], 16;" :: "r"(dst), "l"(src)
               : "memory");
}
#define CP_COMMIT() asm volatile("cp.async.commit_group;" ::: "memory")
#define CP_WAIT(n) asm volatile("cp.async.wait_group %0;" :: "n"(n) : "memory")

// split 8 fp32 -> hi,lo bf16x8 (packed as 4x u32 each)
__device__ __forceinline__ void split8(const float* v, uint4& hi, uint4& lo) {
  uint32_t h[4], l[4];
#pragma unroll
  for (int q = 0; q < 4; q++) {
    float a = v[2 * q], b = v[2 * q + 1];
    __nv_bfloat16 ah = __float2bfloat16_rn(a), bh = __float2bfloat16_rn(b);
    __nv_bfloat162 hv; hv.x = ah; hv.y = bh; h[q] = *(uint32_t*)&hv;
    __nv_bfloat162 lv;
    lv.x = __float2bfloat16_rn(a - __bfloat162float(ah));
    lv.y = __float2bfloat16_rn(b - __bfloat162float(bh));
    l[q] = *(uint32_t*)&lv;
  }
  hi = make_uint4(h[0], h[1], h[2], h[3]);
  lo = make_uint4(l[0], l[1], l[2], l[3]);
}

// ============================================================================
// K1: h = x @ W^T. 128 CTAs: M-tile 128, N = 256 (full), K = 256 in 8x32.
// 8 warps as 2(M) x 4(N), warp tile 64x64. Split-3.
// smem: Ah[128][40] Al | Bh[256][40] Bl | a[512] | red bufs
// ============================================================================
#define K1_AH 0
#define K1_AL 10240
#define K1_BH 20480
#define K1_BL 40960
#define K1_AS 61440
#define K1_R1 63488
#define K1_R2 65536
#define K1_SMEM 67584

__global__ __launch_bounds__(256, 1) void k1(
    const float* __restrict__ x, const float* __restrict__ W,
    const float* __restrict__ a) {
  extern __shared__ char sm[];
  const uint32_t SB = smem_u32(sm);
  const int t = threadIdx.x, lane = t & 31, wid = t >> 5;
  const int warpM = wid >> 2, warpN = wid & 3;
  const int i0 = blockIdx.x * 128;

  ((float*)(sm + K1_AS))[t] = a[t];
  ((float*)(sm + K1_AS))[t + 256] = a[t + 256];

  float c[4][8][4];
#pragma unroll
  for (int r = 0; r < 4; r++)
#pragma unroll
    for (int f = 0; f < 8; f++)
#pragma unroll
      for (int q = 0; q < 4; q++) c[r][f][q] = 0.f;

  for (int ch = 0; ch < 8; ch++) {
    const int k0 = ch * 32;
    // A tile: x[i0+row][k0+colh .. +15]
    {
      const int row = t >> 1, colh = (t & 1) * 16;
      float v[16];
#pragma unroll
      for (int q = 0; q < 4; q++)
        *(float4*)&v[q * 4] =
            *(const float4*)&x[(size_t)(i0 + row) * 256 + k0 + colh + q * 4];
      uint4 h0, l0, h1, l1;
      split8(v, h0, l0); split8(v + 8, h1, l1);
      const uint32_t off = (uint32_t)(row * 40 + colh) * 2;
      *(uint4*)(sm + K1_AH + off) = h0; *(uint4*)(sm + K1_AH + off + 16) = h1;
      *(uint4*)(sm + K1_AL + off) = l0; *(uint4*)(sm + K1_AL + off + 16) = l1;
    }
    // B tile: W[t][k0 .. +31]
    {
      float v[32];
#pragma unroll
      for (int q = 0; q < 8; q++)
        *(float4*)&v[q * 4] = *(const float4*)&W[(size_t)t * 256 + k0 + q * 4];
      const uint32_t off = (uint32_t)(t * 40) * 2;
#pragma unroll
      for (int g = 0; g < 2; g++) {
        uint4 hh, ll;
        split8(v + g * 16, hh, ll);
        *(uint4*)(sm + K1_BH + off + g * 32) = hh;
        *(uint4*)(sm + K1_BL + off + g * 32) = ll;
        uint4 hh2, ll2;
        split8(v + g * 16 + 8, hh2, ll2);
        *(uint4*)(sm + K1_BH + off + g * 32 + 16) = hh2;
        *(uint4*)(sm + K1_BL + off + g * 32 + 16) = ll2;
      }
    }
    __syncthreads();
#pragma unroll
    for (int ks = 0; ks < 32; ks += 16) {
      const uint32_t lrow = (uint32_t)(lane & 15);
      const uint32_t lcol = (uint32_t)(ks + ((lane >> 4) << 3));
      uint32_t ah[4][4], al[4][4];
#pragma unroll
      for (int r = 0; r < 4; r++) {
        uint32_t ra = SB + ((warpM * 64 + r * 16 + lrow) * 40 + lcol) * 2;
        ldsm4(ra + K1_AH, ah[r]);
        ldsm4(ra + K1_AL, al[r]);
      }
      uint32_t bh[8][2], bl[8][2];
#pragma unroll
      for (int q = 0; q < 4; q++) {
        uint32_t rb = SB + ((warpN * 64 + q * 16 + lrow) * 40 + lcol) * 2;
        uint32_t rr[4];
        ldsm4(rb + K1_BH, rr);
        bh[2 * q][0] = rr[0]; bh[2 * q + 1][0] = rr[1];
        bh[2 * q][1] = rr[2]; bh[2 * q + 1][1] = rr[3];
        ldsm4(rb + K1_BL, rr);
        bl[2 * q][0] = rr[0]; bl[2 * q + 1][0] = rr[1];
        bl[2 * q][1] = rr[2]; bl[2 * q + 1][1] = rr[3];
      }
#pragma unroll
      for (int r = 0; r < 4; r++)
#pragma unroll
        for (int f = 0; f < 8; f++) mma16816(c[r][f], ah[r], bh[f][0], bh[f][1]);
#pragma unroll
      for (int r = 0; r < 4; r++)
#pragma unroll
        for (int f = 0; f < 8; f++) mma16816(c[r][f], ah[r], bl[f][0], bl[f][1]);
#pragma unroll
      for (int r = 0; r < 4; r++)
#pragma unroll
        for (int f = 0; f < 8; f++) mma16816(c[r][f], al[r], bh[f][0], bh[f][1]);
    }
    __syncthreads();
  }

  // ---- epilogue: s1/s2 partials + h hi/lo stores ----
  const float* as_ = (const float*)(sm + K1_AS);
  float s1p[8], s2p[8];
#pragma unroll
  for (int q = 0; q < 8; q++) { s1p[q] = 0.f; s2p[q] = 0.f; }
#pragma unroll
  for (int r = 0; r < 4; r++)
#pragma unroll
    for (int f = 0; f < 8; f++)
#pragma unroll
      for (int q = 0; q < 4; q++) {
        int col = warpN * 64 + f * 8 + 2 * (lane & 3) + (q & 1);
        int ri = r * 2 + (q >> 1);
        s1p[ri] += c[r][f][q] * as_[col];
        s2p[ri] += c[r][f][q] * as_[256 + col];
      }
#pragma unroll
  for (int o = 1; o < 4; o <<= 1)
#pragma unroll
    for (int ri = 0; ri < 8; ri++) {
      s1p[ri] += __shfl_xor_sync(0xffffffffu, s1p[ri], o);
      s2p[ri] += __shfl_xor_sync(0xffffffffu, s2p[ri], o);
    }
  if ((lane & 3) == 0) {
#pragma unroll
    for (int r = 0; r < 4; r++)
#pragma unroll
      for (int hh = 0; hh < 2; hh++) {
        int rowr = warpM * 64 + r * 16 + (lane >> 2) + hh * 8;
        ((float*)(sm + K1_R1))[warpN * 128 + rowr] = s1p[r * 2 + hh];
        ((float*)(sm + K1_R2))[warpN * 128 + rowr] = s2p[r * 2 + hh];
      }
  }
  // h stores
#pragma unroll
  for (int r = 0; r < 4; r++)
#pragma unroll
    for (int f = 0; f < 8; f++) {
      int row0 = i0 + warpM * 64 + r * 16 + (lane >> 2);
      int col0 = warpN * 64 + f * 8 + 2 * (lane & 3);
#pragma unroll
      for (int hh = 0; hh < 2; hh++) {
        float v0 = c[r][f][hh * 2], v1 = c[r][f][hh * 2 + 1];
        size_t base = (size_t)(row0 + hh * 8) * 256 + col0;
        __nv_bfloat16 h0 = __float2bfloat16_rn(v0);
        __nv_bfloat16 h1 = __float2bfloat16_rn(v1);
        __nv_bfloat162 ph; ph.x = h0; ph.y = h1;
        *(uint32_t*)&g_h_hi[base] = *(uint32_t*)&ph;
        __nv_bfloat162 pl;
        pl.x = __float2bfloat16_rn(v0 - __bfloat162float(h0));
        pl.y = __float2bfloat16_rn(v1 - __bfloat162float(h1));
        *(uint32_t*)&g_h_lo[base] = *(uint32_t*)&pl;
      }
    }
  __syncthreads();
  if (t < 128) {
    const float* r1 = (const float*)(sm + K1_R1);
    const float* r2 = (const float*)(sm + K1_R2);
    float v1 = 0.f, v2 = 0.f;
#pragma unroll
    for (int wn = 0; wn < 4; wn++) { v1 += r1[wn * 128 + t]; v2 += r2[wn * 128 + t]; }
    g_s1[i0 + t] = v1;
    g_s2[i0 + t] = v2;
  }
}

// ============================================================================
// K2: attention. 128 CTAs = 8 batch x 16 i-tiles. CTA M=128, N=256, K=2048
// in 64 chunks of 32. 3-stage cp.async ring for h (hi/lo); w bf16 on the fly;
// denominator from bf16 w (consistent); split-2 mma.
// ============================================================================
#define ATB_STG 16896              // [32][264] bf16
#define AT_BH 0                    // 3 stages
#define AT_BL 50688
#define AT_A 101376                // [128][40] bf16
#define AT_S2 111616               // 2048 f32
#define AT_S1 119808               // 128 f32
#define AT_DB 120320               // 256 f32
#define AT_DEN 121344              // 128 f32
#define AT_SMEM 121856

__global__ __launch_bounds__(256, 1) void k2(float* __restrict__ out) {
  extern __shared__ char sm[];
  const uint32_t SB = smem_u32(sm);
  const int t = threadIdx.x, lane = t & 31, wid = t >> 5;
  const int warpM = wid >> 2, warpN = wid & 3;
  const int b = blockIdx.x >> 4;
  const int i0 = (blockIdx.x & 15) * 128;

  if (t < 128) ((float*)(sm + AT_S1))[t] = g_s1[b * 2048 + i0 + t];
#pragma unroll
  for (int j = t; j < 2048; j += 256)
    ((float*)(sm + AT_S2))[j] = g_s2[b * 2048 + j];
  __syncthreads();

  const float* s2s = (const float*)(sm + AT_S2);
  const float s1v = ((const float*)(sm + AT_S1))[t >> 1];
  const __nv_bfloat16* Hh = g_h_hi + (size_t)b * 2048 * 256;
  const __nv_bfloat16* Hl = g_h_lo + (size_t)b * 2048 * 256;

  float c[4][8][4];
#pragma unroll
  for (int r = 0; r < 4; r++)
#pragma unroll
    for (int f = 0; f < 8; f++)
#pragma unroll
      for (int q = 0; q < 4; q++) c[r][f][q] = 0.f;
  float dtot = 0.f;

  // cp.async issue of chunk pc into stage pc%3 (4 hi + 4 lo x 16B per thread)
  const int ldrow = t >> 3;              // reused: u = v*256+t -> row=(u>>5)
#pragma unroll
  for (int pc = 0; pc < 2; pc++) {
    const uint32_t dh = SB + AT_BH + (pc % 3) * ATB_STG;
    const uint32_t dl = SB + AT_BL + (pc % 3) * ATB_STG;
    const int j0 = pc * 32;
#pragma unroll
    for (int v = 0; v < 4; v++) {
      int u = v * 256 + t, row = u >> 5, seg = u & 31;
      uint32_t doff = (uint32_t)(row * 264 + seg * 8) * 2;
      size_t soff = (size_t)(j0 + row) * 256 + seg * 8;
      cpa16(dh + doff, Hh + soff);
      cpa16(dl + doff, Hl + soff);
    }
    CP_COMMIT();
  }
  (void)ldrow;

  for (int n = 0; n < 64; n++) {
    // a) prefetch chunk n+2
    if (n + 2 < 64) {
      const uint32_t dh = SB + AT_BH + ((n + 2) % 3) * ATB_STG;
      const uint32_t dl = SB + AT_BL + ((n + 2) % 3) * ATB_STG;
      const int j0 = (n + 2) * 32;
#pragma unroll
      for (int v = 0; v < 4; v++) {
        int u = v * 256 + t, row = u >> 5, seg = u & 31;
        uint32_t doff = (uint32_t)(row * 264 + seg * 8) * 2;
        size_t soff = (size_t)(j0 + row) * 256 + seg * 8;
        cpa16(dh + doff, Hh + soff);
        cpa16(dl + doff, Hl + soff);
      }
    }
    CP_COMMIT();

    // b) generate w chunk n (bf16, denominator from rounded values)
    {
      const int m = t >> 1, kh = (t & 1) * 16;
      const int j0 = n * 32;
      uint32_t pkk[8];
#pragma unroll
      for (int q = 0; q < 8; q++) {
        float e0 = s1v + s2s[j0 + kh + 2 * q];
        float e1 = s1v + s2s[j0 + kh + 2 * q + 1];
        e0 = fmaxf(e0, NEG_SLOPE * e0);
        e1 = fmaxf(e1, NEG_SLOPE * e1);
        __nv_bfloat16 w0 = __float2bfloat16_rn(__expf(e0));
        __nv_bfloat16 w1 = __float2bfloat16_rn(__expf(e1));
        dtot += __bfloat162float(w0) + __bfloat162float(w1);
        __nv_bfloat162 p; p.x = w0; p.y = w1;
        pkk[q] = *(uint32_t*)&p;
      }
      const uint32_t off = (uint32_t)(m * 40 + kh) * 2;
      *(uint4*)(sm + AT_A + off) = make_uint4(pkk[0], pkk[1], pkk[2], pkk[3]);
      *(uint4*)(sm + AT_A + off + 16) = make_uint4(pkk[4], pkk[5], pkk[6], pkk[7]);
    }

    CP_WAIT(2);
    __syncthreads();

    // c) mma chunk n
    const uint32_t Bh = SB + AT_BH + (n % 3) * ATB_STG;
    const uint32_t Bl = SB + AT_BL + (n % 3) * ATB_STG;
#pragma unroll
    for (int ks = 0; ks < 32; ks += 16) {
      uint32_t ah[4][4];
#pragma unroll
      for (int r = 0; r < 4; r++)
        ldsm4(SB + AT_A +
                  ((warpM * 64 + r * 16 + (lane & 15)) * 40 + ks +
                   ((lane >> 4) << 3)) * 2,
              ah[r]);
      const uint32_t roff =
          (uint32_t)(ks + ((lane >> 3) & 1) * 8 + (lane & 7)) * 264;
      uint32_t bh[8][2], bl[8][2];
#pragma unroll
      for (int q = 0; q < 4; q++) {
        uint32_t coff = (uint32_t)(warpN * 64 + q * 16 + ((lane >> 4) << 3));
        uint32_t rr[4];
        ldsm4t(Bh + (roff + coff) * 2, rr);
        bh[2 * q][0] = rr[0]; bh[2 * q][1] = rr[1];
        bh[2 * q + 1][0] = rr[2]; bh[2 * q + 1][1] = rr[3];
        ldsm4t(Bl + (roff + coff) * 2, rr);
        bl[2 * q][0] = rr[0]; bl[2 * q][1] = rr[1];
        bl[2 * q + 1][0] = rr[2]; bl[2 * q + 1][1] = rr[3];
      }
#pragma unroll
      for (int r = 0; r < 4; r++)
#pragma unroll
        for (int f = 0; f < 8; f++) mma16816(c[r][f], ah[r], bh[f][0], bh[f][1]);
#pragma unroll
      for (int r = 0; r < 4; r++)
#pragma unroll
        for (int f = 0; f < 8; f++) mma16816(c[r][f], ah[r], bl[f][0], bl[f][1]);
    }
    __syncthreads();
  }

  // ---- denominator + epilogue ----
  ((float*)(sm + AT_DB))[(t >> 1) * 2 + (t & 1)] = dtot;
  __syncthreads();
  if (t < 128) {
    const float* db = (const float*)(sm + AT_DB);
    ((float*)(sm + AT_DEN))[t] = db[2 * t] + db[2 * t + 1];
  }
  __syncthreads();
  const float* den = (const float*)(sm + AT_DEN);
  float inv[8];
#pragma unroll
  for (int r = 0; r < 4; r++)
#pragma unroll
    for (int hh = 0; hh < 2; hh++)
      inv[r * 2 + hh] =
          1.0f / den[warpM * 64 + r * 16 + (lane >> 2) + hh * 8];

  float* ob = out + ((size_t)b * 2048 + i0) * 256;
#pragma unroll
  for (int r = 0; r < 4; r++)
#pragma unroll
    for (int f = 0; f < 8; f++) {
      int col = warpN * 64 + f * 8 + 2 * (lane & 3);
#pragma unroll
      for (int hh = 0; hh < 2; hh++) {
        int row = warpM * 64 + r * 16 + (lane >> 2) + hh * 8;
        float iv = inv[r * 2 + hh];
        float v0 = c[r][f][hh * 2] * iv;
        float v1 = c[r][f][hh * 2 + 1] * iv;
        v0 = v0 > 0.f ? v0 : expm1f(v0);
        v1 = v1 > 0.f ? v1 : expm1f(v1);
        *(float2*)&ob[(size_t)row * 256 + col] = make_float2(v0, v1);
      }
    }
}

// ============================================================================
extern "C" void kernel_launch(void* const* d_in, const int* in_sizes, int n_in,
                              void* d_out, int out_size) {
  (void)in_sizes; (void)n_in; (void)out_size;
  const float* x = (const float*)d_in[0];
  const float* W = (const float*)d_in[1];
  const float* a = (const float*)d_in[2];
  float* out = (float*)d_out;

  cudaFuncSetAttribute(k1, cudaFuncAttributeMaxDynamicSharedMemorySize, K1_SMEM);
  cudaFuncSetAttribute(k2, cudaFuncAttributeMaxDynamicSharedMemorySize, AT_SMEM);

  k1<<<128, 256, K1_SMEM>>>(x, W, a);
  k2<<<128, 256, AT_SMEM>>>(out);
}

// round 4
// speedup vs baseline: 4.2474x; 1.6058x over previous
#include <cuda_runtime.h>
#include <cuda_fp16.h>
#include <cstdint>

// GraphAttentionLayer B=8,T=2048,D=256 — fp16 mma.sync pipeline.
//  K1: h = x@W^T, split-3 fp16 mma; epilogue: s1/s2 (fp32) + h fp16 store
//  K2: out = elu( (W_att @ h) / den ), w fp16 on the fly, single-term mma,
//      4-stage cp.async ring, double-buffered w tile.

#define B_ 8
#define T_ 2048
#define NEG_SLOPE 0.2f

__device__ __half g_h[B_ * T_ * 256];   // [b][j][o], 8 MB
__device__ float g_s1[B_ * T_];
__device__ float g_s2[B_ * T_];

// ---------------- helpers ----------------------------------------------------
__device__ __forceinline__ uint32_t smem_u32(const void* p) {
  uint32_t a;
  asm("{ .reg .u64 t; cvta.to.shared.u64 t, %1; cvt.u32.u64 %0, t; }"
      : "=r"(a) : "l"(p));
  return a;
}
__device__ __forceinline__ void ldsm4(uint32_t addr, uint32_t r[4]) {
  asm volatile("ldmatrix.sync.aligned.m8n8.x4.shared.b16 {%0,%1,%2,%3}, [%4];"
               : "=r"(r[0]), "=r"(r[1]), "=r"(r[2]), "=r"(r[3]) : "r"(addr));
}
__device__ __forceinline__ void ldsm4t(uint32_t addr, uint32_t r[4]) {
  asm volatile("ldmatrix.sync.aligned.m8n8.x4.trans.shared.b16 {%0,%1,%2,%3}, [%4];"
               : "=r"(r[0]), "=r"(r[1]), "=r"(r[2]), "=r"(r[3]) : "r"(addr));
}
__device__ __forceinline__ void mma16816(float c[4], const uint32_t a[4],
                                         uint32_t b0, uint32_t b1) {
  asm volatile(
      "mma.sync.aligned.m16n8k16.row.col.f32.f16.f16.f32 "
      "{%0,%1,%2,%3}, {%4,%5,%6,%7}, {%8,%9}, {%0,%1,%2,%3};"
      : "+f"(c[0]), "+f"(c[1]), "+f"(c[2]), "+f"(c[3])
      : "r"(a[0]), "r"(a[1]), "r"(a[2]), "r"(a[3]), "r"(b0), "r"(b1));
}
__device__ __forceinline__ void cpa16(uint32_t dst, const void* src) {
  asm volatile("cp.async.cg.shared.global [%0], [%1], 16;" :: "r"(dst), "l"(src)
               : "memory");
}
#define CP_COMMIT() asm volatile("cp.async.commit_group;" ::: "memory")
#define CP_WAIT(n) asm volatile("cp.async.wait_group %0;" :: "n"(n) : "memory")

// split 8 fp32 -> hi,lo fp16x8 (packed as 4x u32 each)
__device__ __forceinline__ void split8(const float* v, uint4& hi, uint4& lo) {
  uint32_t h[4], l[4];
#pragma unroll
  for (int q = 0; q < 4; q++) {
    float a = v[2 * q], b = v[2 * q + 1];
    __half ah = __float2half_rn(a), bh = __float2half_rn(b);
    __half2 hv; hv.x = ah; hv.y = bh; h[q] = *(uint32_t*)&hv;
    __half2 lv;
    lv.x = __float2half_rn(a - __half2float(ah));
    lv.y = __float2half_rn(b - __half2float(bh));
    l[q] = *(uint32_t*)&lv;
  }
  hi = make_uint4(h[0], h[1], h[2], h[3]);
  lo = make_uint4(l[0], l[1], l[2], l[3]);
}

// ============================================================================
// K1: h = x @ W^T. 128 CTAs: M-tile 128, N=256 (full), K=256 in 8x32.
// 8 warps 2(M) x 4(N), warp tile 64x64. Split-3 fp16.
// ============================================================================
#define K1_AH 0
#define K1_AL 10240
#define K1_BH 20480
#define K1_BL 40960
#define K1_AS 61440
#define K1_R1 63488
#define K1_R2 65536
#define K1_SMEM 67584

__global__ __launch_bounds__(256, 1) void k1(
    const float* __restrict__ x, const float* __restrict__ W,
    const float* __restrict__ a) {
  extern __shared__ char sm[];
  const uint32_t SB = smem_u32(sm);
  const int t = threadIdx.x, lane = t & 31, wid = t >> 5;
  const int warpM = wid >> 2, warpN = wid & 3;
  const int i0 = blockIdx.x * 128;

  ((float*)(sm + K1_AS))[t] = a[t];
  ((float*)(sm + K1_AS))[t + 256] = a[t + 256];

  float c[4][8][4];
#pragma unroll
  for (int r = 0; r < 4; r++)
#pragma unroll
    for (int f = 0; f < 8; f++)
#pragma unroll
      for (int q = 0; q < 4; q++) c[r][f][q] = 0.f;

  for (int ch = 0; ch < 8; ch++) {
    const int k0 = ch * 32;
    // A tile: x[i0+row][k0+colh .. +15]
    {
      const int row = t >> 1, colh = (t & 1) * 16;
      float v[16];
#pragma unroll
      for (int q = 0; q < 4; q++)
        *(float4*)&v[q * 4] =
            *(const float4*)&x[(size_t)(i0 + row) * 256 + k0 + colh + q * 4];
      uint4 h0, l0, h1, l1;
      split8(v, h0, l0); split8(v + 8, h1, l1);
      const uint32_t off = (uint32_t)(row * 40 + colh) * 2;
      *(uint4*)(sm + K1_AH + off) = h0; *(uint4*)(sm + K1_AH + off + 16) = h1;
      *(uint4*)(sm + K1_AL + off) = l0; *(uint4*)(sm + K1_AL + off + 16) = l1;
    }
    // B tile: W[t][k0 .. +31]
    {
      float v[32];
#pragma unroll
      for (int q = 0; q < 8; q++)
        *(float4*)&v[q * 4] = *(const float4*)&W[(size_t)t * 256 + k0 + q * 4];
      const uint32_t off = (uint32_t)(t * 40) * 2;
#pragma unroll
      for (int g = 0; g < 2; g++) {
        uint4 hh, ll;
        split8(v + g * 16, hh, ll);
        *(uint4*)(sm + K1_BH + off + g * 32) = hh;
        *(uint4*)(sm + K1_BL + off + g * 32) = ll;
        uint4 hh2, ll2;
        split8(v + g * 16 + 8, hh2, ll2);
        *(uint4*)(sm + K1_BH + off + g * 32 + 16) = hh2;
        *(uint4*)(sm + K1_BL + off + g * 32 + 16) = ll2;
      }
    }
    __syncthreads();
#pragma unroll
    for (int ks = 0; ks < 32; ks += 16) {
      const uint32_t lrow = (uint32_t)(lane & 15);
      const uint32_t lcol = (uint32_t)(ks + ((lane >> 4) << 3));
      uint32_t ah[4][4], al[4][4];
#pragma unroll
      for (int r = 0; r < 4; r++) {
        uint32_t ra = SB + ((warpM * 64 + r * 16 + lrow) * 40 + lcol) * 2;
        ldsm4(ra + K1_AH, ah[r]);
        ldsm4(ra + K1_AL, al[r]);
      }
      uint32_t bh[8][2], bl[8][2];
#pragma unroll
      for (int q = 0; q < 4; q++) {
        uint32_t rb = SB + ((warpN * 64 + q * 16 + lrow) * 40 + lcol) * 2;
        uint32_t rr[4];
        ldsm4(rb + K1_BH, rr);
        bh[2 * q][0] = rr[0]; bh[2 * q + 1][0] = rr[1];
        bh[2 * q][1] = rr[2]; bh[2 * q + 1][1] = rr[3];
        ldsm4(rb + K1_BL, rr);
        bl[2 * q][0] = rr[0]; bl[2 * q + 1][0] = rr[1];
        bl[2 * q][1] = rr[2]; bl[2 * q + 1][1] = rr[3];
      }
#pragma unroll
      for (int r = 0; r < 4; r++)
#pragma unroll
        for (int f = 0; f < 8; f++) mma16816(c[r][f], ah[r], bh[f][0], bh[f][1]);
#pragma unroll
      for (int r = 0; r < 4; r++)
#pragma unroll
        for (int f = 0; f < 8; f++) mma16816(c[r][f], ah[r], bl[f][0], bl[f][1]);
#pragma unroll
      for (int r = 0; r < 4; r++)
#pragma unroll
        for (int f = 0; f < 8; f++) mma16816(c[r][f], al[r], bh[f][0], bh[f][1]);
    }
    __syncthreads();
  }

  // ---- epilogue: s1/s2 partials + h fp16 stores ----
  const float* as_ = (const float*)(sm + K1_AS);
  float s1p[8], s2p[8];
#pragma unroll
  for (int q = 0; q < 8; q++) { s1p[q] = 0.f; s2p[q] = 0.f; }
#pragma unroll
  for (int r = 0; r < 4; r++)
#pragma unroll
    for (int f = 0; f < 8; f++)
#pragma unroll
      for (int q = 0; q < 4; q++) {
        int col = warpN * 64 + f * 8 + 2 * (lane & 3) + (q & 1);
        int ri = r * 2 + (q >> 1);
        s1p[ri] += c[r][f][q] * as_[col];
        s2p[ri] += c[r][f][q] * as_[256 + col];
      }
#pragma unroll
  for (int o = 1; o < 4; o <<= 1)
#pragma unroll
    for (int ri = 0; ri < 8; ri++) {
      s1p[ri] += __shfl_xor_sync(0xffffffffu, s1p[ri], o);
      s2p[ri] += __shfl_xor_sync(0xffffffffu, s2p[ri], o);
    }
  if ((lane & 3) == 0) {
#pragma unroll
    for (int r = 0; r < 4; r++)
#pragma unroll
      for (int hh = 0; hh < 2; hh++) {
        int rowr = warpM * 64 + r * 16 + (lane >> 2) + hh * 8;
        ((float*)(sm + K1_R1))[warpN * 128 + rowr] = s1p[r * 2 + hh];
        ((float*)(sm + K1_R2))[warpN * 128 + rowr] = s2p[r * 2 + hh];
      }
  }
  // h stores (fp16 only)
#pragma unroll
  for (int r = 0; r < 4; r++)
#pragma unroll
    for (int f = 0; f < 8; f++) {
      int row0 = i0 + warpM * 64 + r * 16 + (lane >> 2);
      int col0 = warpN * 64 + f * 8 + 2 * (lane & 3);
#pragma unroll
      for (int hh = 0; hh < 2; hh++) {
        size_t base = (size_t)(row0 + hh * 8) * 256 + col0;
        __half2 ph;
        ph.x = __float2half_rn(c[r][f][hh * 2]);
        ph.y = __float2half_rn(c[r][f][hh * 2 + 1]);
        *(uint32_t*)&g_h[base] = *(uint32_t*)&ph;
      }
    }
  __syncthreads();
  if (t < 128) {
    const float* r1 = (const float*)(sm + K1_R1);
    const float* r2 = (const float*)(sm + K1_R2);
    float v1 = 0.f, v2 = 0.f;
#pragma unroll
    for (int wn = 0; wn < 4; wn++) { v1 += r1[wn * 128 + t]; v2 += r2[wn * 128 + t]; }
    g_s1[i0 + t] = v1;
    g_s2[i0 + t] = v2;
  }
}

// ============================================================================
// K2: attention. 128 CTAs = 8 batch x 16 i-tiles. CTA M=128, N=256, K=2048
// in 32 chunks of 64. 4-stage cp.async ring for h; w fp16 on the fly into a
// double-buffered A tile; single-term mma; den from rounded w.
// ============================================================================
#define ATB 0                     // 4 stages x [64][264] fp16
#define ATB_STG 33792
#define AT_A 135168               // 2 x [128][72] fp16
#define AT_AST 18432
#define AT_S2 172032              // 2048 f32
#define AT_S1 180224              // 128 f32
#define AT_DB 180736              // 256 f32
#define AT_DEN 181760             // 128 f32
#define AT_SMEM 182272

__global__ __launch_bounds__(256, 1) void k2(float* __restrict__ out) {
  extern __shared__ char sm[];
  const uint32_t SB = smem_u32(sm);
  const int t = threadIdx.x, lane = t & 31, wid = t >> 5;
  const int warpM = wid >> 2, warpN = wid & 3;
  const int b = blockIdx.x >> 4;
  const int i0 = (blockIdx.x & 15) * 128;

  if (t < 128) ((float*)(sm + AT_S1))[t] = g_s1[b * 2048 + i0 + t];
#pragma unroll
  for (int j = t; j < 2048; j += 256)
    ((float*)(sm + AT_S2))[j] = g_s2[b * 2048 + j];
  __syncthreads();

  const float* s2s = (const float*)(sm + AT_S2);
  const float s1v = ((const float*)(sm + AT_S1))[t >> 1];
  const __half* H = g_h + (size_t)b * 2048 * 256;

  float c[4][8][4];
#pragma unroll
  for (int r = 0; r < 4; r++)
#pragma unroll
    for (int f = 0; f < 8; f++)
#pragma unroll
      for (int q = 0; q < 4; q++) c[r][f][q] = 0.f;
  float dtot = 0.f;

  const int gm = t >> 1, gkh = (t & 1) * 32;  // w-gen ownership

  // ---- gen w for chunk nn into buffer abuf ----
#define GENW(nn, abuf) do {                                                   \
    const int j0_ = (nn) * 64;                                                \
    uint32_t pkk[16];                                                         \
_Pragma("unroll")                                                             \
    for (int q = 0; q < 16; q++) {                                            \
      float e0 = s1v + s2s[j0_ + gkh + 2 * q];                                \
      float e1 = s1v + s2s[j0_ + gkh + 2 * q + 1];                            \
      e0 = fmaxf(e0, NEG_SLOPE * e0);                                         \
      e1 = fmaxf(e1, NEG_SLOPE * e1);                                         \
      __half w0 = __float2half_rn(__expf(e0));                                \
      __half w1 = __float2half_rn(__expf(e1));                                \
      dtot += __half2float(w0) + __half2float(w1);                            \
      __half2 p; p.x = w0; p.y = w1;                                          \
      pkk[q] = *(uint32_t*)&p;                                                \
    }                                                                         \
    const uint32_t off_ = (uint32_t)(gm * 72 + gkh) * 2;                      \
_Pragma("unroll")                                                             \
    for (int g = 0; g < 4; g++)                                               \
      *(uint4*)((abuf) + off_ + g * 16) =                                     \
          make_uint4(pkk[4 * g], pkk[4 * g + 1], pkk[4 * g + 2], pkk[4 * g + 3]); \
  } while (0)

  // ---- cp.async of chunk nn into stage buffer ----
#define LOADB(nn) do {                                                        \
    const uint32_t dst_ = SB + ATB + ((nn) & 3) * ATB_STG;                    \
    const int j0_ = (nn) * 64;                                                \
_Pragma("unroll")                                                             \
    for (int v = 0; v < 8; v++) {                                             \
      int u = v * 256 + t, row = u >> 5, seg = u & 31;                        \
      cpa16(dst_ + (uint32_t)(row * 264 + seg * 8) * 2,                       \
            H + (size_t)(j0_ + row) * 256 + seg * 8);                         \
    }                                                                         \
  } while (0)

  // prologue
  GENW(0, sm + AT_A);
#pragma unroll
  for (int pc = 0; pc < 3; pc++) { LOADB(pc); CP_COMMIT(); }
  CP_WAIT(2);
  __syncthreads();

  for (int n = 0; n < 32; n++) {
    const int p = n & 1;
    const uint32_t Bst = SB + ATB + (n & 3) * ATB_STG;
    const uint32_t Ab = SB + AT_A + p * AT_AST;

    // mma chunk n
#pragma unroll
    for (int ks = 0; ks < 64; ks += 16) {
      uint32_t ah[4][4];
#pragma unroll
      for (int r = 0; r < 4; r++)
        ldsm4(Ab + ((warpM * 64 + r * 16 + (lane & 15)) * 72 + ks +
                    ((lane >> 4) << 3)) * 2,
              ah[r]);
      const uint32_t roff =
          (uint32_t)(ks + ((lane >> 3) & 1) * 8 + (lane & 7)) * 264;
      uint32_t bh[8][2];
#pragma unroll
      for (int q = 0; q < 4; q++) {
        uint32_t coff = (uint32_t)(warpN * 64 + q * 16 + ((lane >> 4) << 3));
        uint32_t rr[4];
        ldsm4t(Bst + (roff + coff) * 2, rr);
        bh[2 * q][0] = rr[0]; bh[2 * q][1] = rr[1];
        bh[2 * q + 1][0] = rr[2]; bh[2 * q + 1][1] = rr[3];
      }
#pragma unroll
      for (int r = 0; r < 4; r++)
#pragma unroll
        for (int f = 0; f < 8; f++) mma16816(c[r][f], ah[r], bh[f][0], bh[f][1]);
    }

    // overlap: gen w for chunk n+1, prefetch chunk n+3
    if (n < 31) GENW(n + 1, sm + AT_A + (p ^ 1) * AT_AST);
    if (n + 3 < 32) LOADB(n + 3);
    CP_COMMIT();
    CP_WAIT(2);
    __syncthreads();
  }

  // ---- denominator + epilogue ----
  ((float*)(sm + AT_DB))[t] = dtot;
  __syncthreads();
  if (t < 128) {
    const float* db = (const float*)(sm + AT_DB);
    ((float*)(sm + AT_DEN))[t] = db[2 * t] + db[2 * t + 1];
  }
  __syncthreads();
  const float* den = (const float*)(sm + AT_DEN);
  float inv[8];
#pragma unroll
  for (int r = 0; r < 4; r++)
#pragma unroll
    for (int hh = 0; hh < 2; hh++)
      inv[r * 2 + hh] =
          1.0f / den[warpM * 64 + r * 16 + (lane >> 2) + hh * 8];

  float* ob = out + ((size_t)b * 2048 + i0) * 256;
#pragma unroll
  for (int r = 0; r < 4; r++)
#pragma unroll
    for (int f = 0; f < 8; f++) {
      int col = warpN * 64 + f * 8 + 2 * (lane & 3);
#pragma unroll
      for (int hh = 0; hh < 2; hh++) {
        int row = warpM * 64 + r * 16 + (lane >> 2) + hh * 8;
        float iv = inv[r * 2 + hh];
        float v0 = c[r][f][hh * 2] * iv;
        float v1 = c[r][f][hh * 2 + 1] * iv;
        v0 = v0 > 0.f ? v0 : expm1f(v0);
        v1 = v1 > 0.f ? v1 : expm1f(v1);
        *(float2*)&ob[(size_t)row * 256 + col] = make_float2(v0, v1);
      }
    }
}

// ============================================================================
extern "C" void kernel_launch(void* const* d_in, const int* in_sizes, int n_in,
                              void* d_out, int out_size) {
  (void)in_sizes; (void)n_in; (void)out_size;
  const float* x = (const float*)d_in[0];
  const float* W = (const float*)d_in[1];
  const float* a = (const float*)d_in[2];
  float* out = (float*)d_out;

  cudaFuncSetAttribute(k1, cudaFuncAttributeMaxDynamicSharedMemorySize, K1_SMEM);
  cudaFuncSetAttribute(k2, cudaFuncAttributeMaxDynamicSharedMemorySize, AT_SMEM);

  k1<<<128, 256, K1_SMEM>>>(x, W, a);
  k2<<<128, 256, AT_SMEM>>>(out);
}

// round 5
// speedup vs baseline: 4.6438x; 1.0933x over previous
#include <cuda_runtime.h>
#include <cuda_fp16.h>
#include <cstdint>

// GraphAttentionLayer B=8,T=2048,D=256 — fp16 mma.sync, 512-thread CTAs.
//  K1: h = x@W^T, split-3 fp16; epilogue: s1/s2 + h fp16 store
//  K2: out = elu( (W_att @ h) / den ), w fp16 on the fly, single-term mma

#define B_ 8
#define T_ 2048
#define NEG_SLOPE 0.2f

__device__ __half g_h[B_ * T_ * 256];   // [b][j][o], 8 MB
__device__ float g_s1[B_ * T_];
__device__ float g_s2[B_ * T_];

// ---------------- helpers ----------------------------------------------------
__device__ __forceinline__ uint32_t smem_u32(const void* p) {
  uint32_t a;
  asm("{ .reg .u64 t; cvta.to.shared.u64 t, %1; cvt.u32.u64 %0, t; }"
      : "=r"(a) : "l"(p));
  return a;
}
__device__ __forceinline__ void ldsm4(uint32_t addr, uint32_t r[4]) {
  asm volatile("ldmatrix.sync.aligned.m8n8.x4.shared.b16 {%0,%1,%2,%3}, [%4];"
               : "=r"(r[0]), "=r"(r[1]), "=r"(r[2]), "=r"(r[3]) : "r"(addr));
}
__device__ __forceinline__ void ldsm4t(uint32_t addr, uint32_t r[4]) {
  asm volatile("ldmatrix.sync.aligned.m8n8.x4.trans.shared.b16 {%0,%1,%2,%3}, [%4];"
               : "=r"(r[0]), "=r"(r[1]), "=r"(r[2]), "=r"(r[3]) : "r"(addr));
}
__device__ __forceinline__ void mma16816(float c[4], const uint32_t a[4],
                                         uint32_t b0, uint32_t b1) {
  asm volatile(
      "mma.sync.aligned.m16n8k16.row.col.f32.f16.f16.f32 "
      "{%0,%1,%2,%3}, {%4,%5,%6,%7}, {%8,%9}, {%0,%1,%2,%3};"
      : "+f"(c[0]), "+f"(c[1]), "+f"(c[2]), "+f"(c[3])
      : "r"(a[0]), "r"(a[1]), "r"(a[2]), "r"(a[3]), "r"(b0), "r"(b1));
}
__device__ __forceinline__ void cpa16(uint32_t dst, const void* src) {
  asm volatile("cp.async.cg.shared.global [%0], [%1], 16;" :: "r"(dst), "l"(src)
               : "memory");
}
#define CP_COMMIT() asm volatile("cp.async.commit_group;" ::: "memory")
#define CP_WAIT(n) asm volatile("cp.async.wait_group %0;" :: "n"(n) : "memory")

// split 8 fp32 -> hi,lo fp16x8
__device__ __forceinline__ void split8(const float* v, uint4& hi, uint4& lo) {
  uint32_t h[4], l[4];
#pragma unroll
  for (int q = 0; q < 4; q++) {
    float a = v[2 * q], b = v[2 * q + 1];
    __half ah = __float2half_rn(a), bh = __float2half_rn(b);
    __half2 hv; hv.x = ah; hv.y = bh; h[q] = *(uint32_t*)&hv;
    __half2 lv;
    lv.x = __float2half_rn(a - __half2float(ah));
    lv.y = __float2half_rn(b - __half2float(bh));
    l[q] = *(uint32_t*)&lv;
  }
  hi = make_uint4(h[0], h[1], h[2], h[3]);
  lo = make_uint4(l[0], l[1], l[2], l[3]);
}

// ============================================================================
// K1: h = x @ W^T. 128 CTAs, 512 threads, warp grid 4x4 (warp tile 32x64).
// K=256 in 4 chunks of 64. Split-3 fp16.
// ============================================================================
#define K1_AH 0                    // [128][72] fp16 = 18432
#define K1_AL 18432
#define K1_BH 36864                // [256][72] fp16 = 36864
#define K1_BL 73728
#define K1_AS 110592               // a[512] f32
#define K1_R1 112640               // [4][128] f32
#define K1_R2 114688
#define K1_SMEM 116736

__global__ __launch_bounds__(512, 1) void k1(
    const float* __restrict__ x, const float* __restrict__ W,
    const float* __restrict__ a) {
  extern __shared__ char sm[];
  const uint32_t SB = smem_u32(sm);
  const int t = threadIdx.x, lane = t & 31, wid = t >> 5;
  const int warpM = wid >> 2, warpN = wid & 3;
  const int i0 = blockIdx.x * 128;

  ((float*)(sm + K1_AS))[t] = a[t];

  float c[2][8][4];
#pragma unroll
  for (int r = 0; r < 2; r++)
#pragma unroll
    for (int f = 0; f < 8; f++)
#pragma unroll
      for (int q = 0; q < 4; q++) c[r][f][q] = 0.f;

  for (int ch = 0; ch < 4; ch++) {
    const int k0 = ch * 64;
    // A tile: x[i0+row][k0 + quad*16 .. +15]
    {
      const int row = t >> 2, quad = t & 3;
      float v[16];
#pragma unroll
      for (int q = 0; q < 4; q++)
        *(float4*)&v[q * 4] =
            *(const float4*)&x[(size_t)(i0 + row) * 256 + k0 + quad * 16 + q * 4];
      uint4 h0, l0, h1, l1;
      split8(v, h0, l0); split8(v + 8, h1, l1);
      const uint32_t off = (uint32_t)(row * 72 + quad * 16) * 2;
      *(uint4*)(sm + K1_AH + off) = h0; *(uint4*)(sm + K1_AH + off + 16) = h1;
      *(uint4*)(sm + K1_AL + off) = l0; *(uint4*)(sm + K1_AL + off + 16) = l1;
    }
    // B tile: W[row][k0 + half .. +31]
    {
      const int row = t >> 1, half = (t & 1) * 32;
      float v[32];
#pragma unroll
      for (int q = 0; q < 8; q++)
        *(float4*)&v[q * 4] =
            *(const float4*)&W[(size_t)row * 256 + k0 + half + q * 4];
      const uint32_t off = (uint32_t)(row * 72 + half) * 2;
#pragma unroll
      for (int g = 0; g < 4; g++) {
        uint4 hh, ll;
        split8(v + g * 8, hh, ll);
        *(uint4*)(sm + K1_BH + off + g * 16) = hh;
        *(uint4*)(sm + K1_BL + off + g * 16) = ll;
      }
    }
    __syncthreads();
#pragma unroll
    for (int ks = 0; ks < 64; ks += 16) {
      const uint32_t lrow = (uint32_t)(lane & 15);
      const uint32_t lcol = (uint32_t)(ks + ((lane >> 4) << 3));
      uint32_t ah[2][4], al[2][4];
#pragma unroll
      for (int r = 0; r < 2; r++) {
        uint32_t ra = SB + ((warpM * 32 + r * 16 + lrow) * 72 + lcol) * 2;
        ldsm4(ra + K1_AH, ah[r]);
        ldsm4(ra + K1_AL, al[r]);
      }
      uint32_t bh[8][2], bl[8][2];
#pragma unroll
      for (int q = 0; q < 4; q++) {
        uint32_t rb = SB + ((warpN * 64 + q * 16 + lrow) * 72 + lcol) * 2;
        uint32_t rr[4];
        ldsm4(rb + K1_BH, rr);
        bh[2 * q][0] = rr[0]; bh[2 * q + 1][0] = rr[1];
        bh[2 * q][1] = rr[2]; bh[2 * q + 1][1] = rr[3];
        ldsm4(rb + K1_BL, rr);
        bl[2 * q][0] = rr[0]; bl[2 * q + 1][0] = rr[1];
        bl[2 * q][1] = rr[2]; bl[2 * q + 1][1] = rr[3];
      }
#pragma unroll
      for (int r = 0; r < 2; r++)
#pragma unroll
        for (int f = 0; f < 8; f++) mma16816(c[r][f], ah[r], bh[f][0], bh[f][1]);
#pragma unroll
      for (int r = 0; r < 2; r++)
#pragma unroll
        for (int f = 0; f < 8; f++) mma16816(c[r][f], ah[r], bl[f][0], bl[f][1]);
#pragma unroll
      for (int r = 0; r < 2; r++)
#pragma unroll
        for (int f = 0; f < 8; f++) mma16816(c[r][f], al[r], bh[f][0], bh[f][1]);
    }
    __syncthreads();
  }

  // ---- epilogue: s1/s2 partials + h fp16 stores ----
  const float* as_ = (const float*)(sm + K1_AS);
  float s1p[4], s2p[4];
#pragma unroll
  for (int q = 0; q < 4; q++) { s1p[q] = 0.f; s2p[q] = 0.f; }
#pragma unroll
  for (int r = 0; r < 2; r++)
#pragma unroll
    for (int f = 0; f < 8; f++)
#pragma unroll
      for (int q = 0; q < 4; q++) {
        int col = warpN * 64 + f * 8 + 2 * (lane & 3) + (q & 1);
        int ri = r * 2 + (q >> 1);
        s1p[ri] += c[r][f][q] * as_[col];
        s2p[ri] += c[r][f][q] * as_[256 + col];
      }
#pragma unroll
  for (int o = 1; o < 4; o <<= 1)
#pragma unroll
    for (int ri = 0; ri < 4; ri++) {
      s1p[ri] += __shfl_xor_sync(0xffffffffu, s1p[ri], o);
      s2p[ri] += __shfl_xor_sync(0xffffffffu, s2p[ri], o);
    }
  if ((lane & 3) == 0) {
#pragma unroll
    for (int r = 0; r < 2; r++)
#pragma unroll
      for (int hh = 0; hh < 2; hh++) {
        int rowr = warpM * 32 + r * 16 + (lane >> 2) + hh * 8;
        ((float*)(sm + K1_R1))[warpN * 128 + rowr] = s1p[r * 2 + hh];
        ((float*)(sm + K1_R2))[warpN * 128 + rowr] = s2p[r * 2 + hh];
      }
  }
  // h stores
#pragma unroll
  for (int r = 0; r < 2; r++)
#pragma unroll
    for (int f = 0; f < 8; f++) {
      int row0 = i0 + warpM * 32 + r * 16 + (lane >> 2);
      int col0 = warpN * 64 + f * 8 + 2 * (lane & 3);
#pragma unroll
      for (int hh = 0; hh < 2; hh++) {
        size_t base = (size_t)(row0 + hh * 8) * 256 + col0;
        __half2 ph;
        ph.x = __float2half_rn(c[r][f][hh * 2]);
        ph.y = __float2half_rn(c[r][f][hh * 2 + 1]);
        *(uint32_t*)&g_h[base] = *(uint32_t*)&ph;
      }
    }
  __syncthreads();
  if (t < 128) {
    const float* r1 = (const float*)(sm + K1_R1);
    const float* r2 = (const float*)(sm + K1_R2);
    float v1 = 0.f, v2 = 0.f;
#pragma unroll
    for (int wn = 0; wn < 4; wn++) { v1 += r1[wn * 128 + t]; v2 += r2[wn * 128 + t]; }
    g_s1[i0 + t] = v1;
    g_s2[i0 + t] = v2;
  }
}

// ============================================================================
// K2: attention. 128 CTAs, 512 threads, warp grid 4x4 (warp tile 32x64).
// CTA M=128, N=256, K=2048 in 32 chunks of 64. 4-stage cp.async ring;
// w fp16 on the fly (double-buffered); single-term mma; den from rounded w.
// ============================================================================
#define ATB 0                     // 4 stages x [64][264] fp16
#define ATB_STG 33792
#define AT_A 135168               // 2 x [128][72] fp16
#define AT_AST 18432
#define AT_S2 172032              // 2048 f32
#define AT_S1 180224              // 128 f32 (512B used of 512 slots)
#define AT_DB 180736              // 512 f32
#define AT_DEN 182784             // 128 f32
#define AT_SMEM 183296

__global__ __launch_bounds__(512, 1) void k2(float* __restrict__ out) {
  extern __shared__ char sm[];
  const uint32_t SB = smem_u32(sm);
  const int t = threadIdx.x, lane = t & 31, wid = t >> 5;
  const int warpM = wid >> 2, warpN = wid & 3;
  const int b = blockIdx.x >> 4;
  const int i0 = (blockIdx.x & 15) * 128;

  if (t < 128) ((float*)(sm + AT_S1))[t] = g_s1[b * 2048 + i0 + t];
#pragma unroll
  for (int j = t; j < 2048; j += 512)
    ((float*)(sm + AT_S2))[j] = g_s2[b * 2048 + j];
  __syncthreads();

  const float* s2s = (const float*)(sm + AT_S2);
  const int gm = t >> 2, gkh = (t & 3) * 16;   // w-gen: row gm, cols gkh..+15
  const float s1v = ((const float*)(sm + AT_S1))[gm];
  const __half* H = g_h + (size_t)b * 2048 * 256;

  float c[2][8][4];
#pragma unroll
  for (int r = 0; r < 2; r++)
#pragma unroll
    for (int f = 0; f < 8; f++)
#pragma unroll
      for (int q = 0; q < 4; q++) c[r][f][q] = 0.f;
  float dtot = 0.f;

#define GENW(nn, abuf) do {                                                   \
    const int j0_ = (nn) * 64;                                                \
    uint32_t pkk[8];                                                          \
_Pragma("unroll")                                                             \
    for (int q = 0; q < 8; q++) {                                             \
      float e0 = s1v + s2s[j0_ + gkh + 2 * q];                                \
      float e1 = s1v + s2s[j0_ + gkh + 2 * q + 1];                            \
      e0 = fmaxf(e0, NEG_SLOPE * e0);                                         \
      e1 = fmaxf(e1, NEG_SLOPE * e1);                                         \
      __half w0 = __float2half_rn(__expf(e0));                                \
      __half w1 = __float2half_rn(__expf(e1));                                \
      dtot += __half2float(w0) + __half2float(w1);                            \
      __half2 p; p.x = w0; p.y = w1;                                          \
      pkk[q] = *(uint32_t*)&p;                                                \
    }                                                                         \
    const uint32_t off_ = (uint32_t)(gm * 72 + gkh) * 2;                      \
    *(uint4*)((abuf) + off_) = make_uint4(pkk[0], pkk[1], pkk[2], pkk[3]);    \
    *(uint4*)((abuf) + off_ + 16) = make_uint4(pkk[4], pkk[5], pkk[6], pkk[7]); \
  } while (0)

#define LOADB(nn) do {                                                        \
    const uint32_t dst_ = SB + ATB + ((nn) & 3) * ATB_STG;                    \
    const int j0_ = (nn) * 64;                                                \
_Pragma("unroll")                                                             \
    for (int v = 0; v < 4; v++) {                                             \
      int u = v * 512 + t, row = u >> 5, seg = u & 31;                        \
      cpa16(dst_ + (uint32_t)(row * 264 + seg * 8) * 2,                       \
            H + (size_t)(j0_ + row) * 256 + seg * 8);                         \
    }                                                                         \
  } while (0)

  // prologue
  GENW(0, sm + AT_A);
#pragma unroll
  for (int pc = 0; pc < 3; pc++) { LOADB(pc); CP_COMMIT(); }
  CP_WAIT(2);
  __syncthreads();

  for (int n = 0; n < 32; n++) {
    const int p = n & 1;
    const uint32_t Bst = SB + ATB + (n & 3) * ATB_STG;
    const uint32_t Ab = SB + AT_A + p * AT_AST;

#pragma unroll
    for (int ks = 0; ks < 64; ks += 16) {
      uint32_t ah[2][4];
#pragma unroll
      for (int r = 0; r < 2; r++)
        ldsm4(Ab + ((warpM * 32 + r * 16 + (lane & 15)) * 72 + ks +
                    ((lane >> 4) << 3)) * 2,
              ah[r]);
      const uint32_t roff =
          (uint32_t)(ks + ((lane >> 3) & 1) * 8 + (lane & 7)) * 264;
      uint32_t bh[8][2];
#pragma unroll
      for (int q = 0; q < 4; q++) {
        uint32_t coff = (uint32_t)(warpN * 64 + q * 16 + ((lane >> 4) << 3));
        uint32_t rr[4];
        ldsm4t(Bst + (roff + coff) * 2, rr);
        bh[2 * q][0] = rr[0]; bh[2 * q][1] = rr[1];
        bh[2 * q + 1][0] = rr[2]; bh[2 * q + 1][1] = rr[3];
      }
#pragma unroll
      for (int r = 0; r < 2; r++)
#pragma unroll
        for (int f = 0; f < 8; f++) mma16816(c[r][f], ah[r], bh[f][0], bh[f][1]);
    }

    // overlap: gen w for chunk n+1 into other A buffer, prefetch chunk n+3
    if (n < 31) GENW(n + 1, sm + AT_A + (p ^ 1) * AT_AST);
    if (n + 3 < 32) LOADB(n + 3);
    CP_COMMIT();
    CP_WAIT(2);
    __syncthreads();
  }

  // ---- denominator + epilogue ----
  ((float*)(sm + AT_DB))[t] = dtot;
  __syncthreads();
  if (t < 128) {
    const float* db = (const float*)(sm + AT_DB);
    ((float*)(sm + AT_DEN))[t] =
        db[4 * t] + db[4 * t + 1] + db[4 * t + 2] + db[4 * t + 3];
  }
  __syncthreads();
  const float* den = (const float*)(sm + AT_DEN);
  float inv[4];
#pragma unroll
  for (int r = 0; r < 2; r++)
#pragma unroll
    for (int hh = 0; hh < 2; hh++)
      inv[r * 2 + hh] =
          1.0f / den[warpM * 32 + r * 16 + (lane >> 2) + hh * 8];

  float* ob = out + ((size_t)b * 2048 + i0) * 256;
#pragma unroll
  for (int r = 0; r < 2; r++)
#pragma unroll
    for (int f = 0; f < 8; f++) {
      int col = warpN * 64 + f * 8 + 2 * (lane & 3);
#pragma unroll
      for (int hh = 0; hh < 2; hh++) {
        int row = warpM * 32 + r * 16 + (lane >> 2) + hh * 8;
        float iv = inv[r * 2 + hh];
        float v0 = c[r][f][hh * 2] * iv;
        float v1 = c[r][f][hh * 2 + 1] * iv;
        v0 = v0 > 0.f ? v0 : expm1f(v0);
        v1 = v1 > 0.f ? v1 : expm1f(v1);
        *(float2*)&ob[(size_t)row * 256 + col] = make_float2(v0, v1);
      }
    }
}

// ============================================================================
extern "C" void kernel_launch(void* const* d_in, const int* in_sizes, int n_in,
                              void* d_out, int out_size) {
  (void)in_sizes; (void)n_in; (void)out_size;
  const float* x = (const float*)d_in[0];
  const float* W = (const float*)d_in[1];
  const float* a = (const float*)d_in[2];
  float* out = (float*)d_out;

  cudaFuncSetAttribute(k1, cudaFuncAttributeMaxDynamicSharedMemorySize, K1_SMEM);
  cudaFuncSetAttribute(k2, cudaFuncAttributeMaxDynamicSharedMemorySize, AT_SMEM);

  k1<<<128, 512, K1_SMEM>>>(x, W, a);
  k2<<<128, 512, AT_SMEM>>>(out);
}

// round 6
// speedup vs baseline: 4.6493x; 1.0012x over previous
#include <cuda_runtime.h>
#include <cuda_fp16.h>
#include <cstdint>

// GraphAttentionLayer B=8,T=2048,D=256 — fp16 mma.sync, 512-thread CTAs.
//  K1: h = x@W^T, split-3 fp16, cp.async-pipelined chunk loads
//  K2: out = elu( (W_att @ h) / den ), K-chunk 128, 2-stage cp.async ring

#define B_ 8
#define T_ 2048
#define NEG_SLOPE 0.2f

__device__ __half g_h[B_ * T_ * 256];   // [b][j][o], 8 MB
__device__ float g_s1[B_ * T_];
__device__ float g_s2[B_ * T_];

// ---------------- helpers ----------------------------------------------------
__device__ __forceinline__ uint32_t smem_u32(const void* p) {
  uint32_t a;
  asm("{ .reg .u64 t; cvta.to.shared.u64 t, %1; cvt.u32.u64 %0, t; }"
      : "=r"(a) : "l"(p));
  return a;
}
__device__ __forceinline__ void ldsm4(uint32_t addr, uint32_t r[4]) {
  asm volatile("ldmatrix.sync.aligned.m8n8.x4.shared.b16 {%0,%1,%2,%3}, [%4];"
               : "=r"(r[0]), "=r"(r[1]), "=r"(r[2]), "=r"(r[3]) : "r"(addr));
}
__device__ __forceinline__ void ldsm4t(uint32_t addr, uint32_t r[4]) {
  asm volatile("ldmatrix.sync.aligned.m8n8.x4.trans.shared.b16 {%0,%1,%2,%3}, [%4];"
               : "=r"(r[0]), "=r"(r[1]), "=r"(r[2]), "=r"(r[3]) : "r"(addr));
}
__device__ __forceinline__ void mma16816(float c[4], const uint32_t a[4],
                                         uint32_t b0, uint32_t b1) {
  asm volatile(
      "mma.sync.aligned.m16n8k16.row.col.f32.f16.f16.f32 "
      "{%0,%1,%2,%3}, {%4,%5,%6,%7}, {%8,%9}, {%0,%1,%2,%3};"
      : "+f"(c[0]), "+f"(c[1]), "+f"(c[2]), "+f"(c[3])
      : "r"(a[0]), "r"(a[1]), "r"(a[2]), "r"(a[3]), "r"(b0), "r"(b1));
}
__device__ __forceinline__ void cpa16(uint32_t dst, const void* src) {
  asm volatile("cp.async.cg.shared.global [%0], [%1], 16;" :: "r"(dst), "l"(src)
               : "memory");
}
#define CP_COMMIT() asm volatile("cp.async.commit_group;" ::: "memory")
#define CP_WAIT(n) asm volatile("cp.async.wait_group %0;" :: "n"(n) : "memory")

// split 8 fp32 -> hi,lo fp16x8
__device__ __forceinline__ void split8(const float* v, uint4& hi, uint4& lo) {
  uint32_t h[4], l[4];
#pragma unroll
  for (int q = 0; q < 4; q++) {
    float a = v[2 * q], b = v[2 * q + 1];
    __half ah = __float2half_rn(a), bh = __float2half_rn(b);
    __half2 hv; hv.x = ah; hv.y = bh; h[q] = *(uint32_t*)&hv;
    __half2 lv;
    lv.x = __float2half_rn(a - __half2float(ah));
    lv.y = __float2half_rn(b - __half2float(bh));
    l[q] = *(uint32_t*)&lv;
  }
  hi = make_uint4(h[0], h[1], h[2], h[3]);
  lo = make_uint4(l[0], l[1], l[2], l[3]);
}

// ============================================================================
// K1: h = x @ W^T. 128 CTAs, 512 threads, warp grid 4x4 (warp tile 32x64).
// K=256 in 4 chunks of 64. Split-3 fp16. cp.async fp32 staging, overlapped.
// ============================================================================
#define K1_FX 0                    // fp32 x tile [128][68] = 34816
#define K1_FW 34816                // fp32 W tile [256][68] = 69632
#define K1_AH 104448               // [128][72] fp16
#define K1_AL 122880
#define K1_BH 141312               // [256][72] fp16
#define K1_BL 178176
#define K1_AS 215040               // a[512] f32
#define K1_R1 217088               // [4][128] f32
#define K1_R2 219136
#define K1_SMEM 221184

__global__ __launch_bounds__(512, 1) void k1(
    const float* __restrict__ x, const float* __restrict__ W,
    const float* __restrict__ a) {
  extern __shared__ char sm[];
  const uint32_t SB = smem_u32(sm);
  const int t = threadIdx.x, lane = t & 31, wid = t >> 5;
  const int warpM = wid >> 2, warpN = wid & 3;
  const int i0 = blockIdx.x * 128;

#define K1_LOADF32(cc) do {                                                   \
    const int k0_ = (cc) * 64;                                                \
    _Pragma("unroll")                                                         \
    for (int v = 0; v < 4; v++) {                                             \
      int u = v * 512 + t, row = u >> 4, seg = u & 15;                        \
      cpa16(SB + K1_FX + (uint32_t)(row * 68 + seg * 4) * 4,                  \
            &x[(size_t)(i0 + row) * 256 + k0_ + seg * 4]);                    \
    }                                                                         \
    _Pragma("unroll")                                                         \
    for (int v = 0; v < 8; v++) {                                             \
      int u = v * 512 + t, row = u >> 4, seg = u & 15;                        \
      cpa16(SB + K1_FW + (uint32_t)(row * 68 + seg * 4) * 4,                  \
            &W[(size_t)row * 256 + k0_ + seg * 4]);                           \
    }                                                                         \
  } while (0)

  K1_LOADF32(0);
  CP_COMMIT();
  ((float*)(sm + K1_AS))[t] = a[t];

  float c[2][8][4];
#pragma unroll
  for (int r = 0; r < 2; r++)
#pragma unroll
    for (int f = 0; f < 8; f++)
#pragma unroll
      for (int q = 0; q < 4; q++) c[r][f][q] = 0.f;

  CP_WAIT(0);
  __syncthreads();

  for (int ch = 0; ch < 4; ch++) {
    // ---- convert fp32 staging -> fp16 hi/lo tiles ----
    {
      const int row = t >> 2, quad = t & 3;
      float v[16];
#pragma unroll
      for (int q = 0; q < 4; q++)
        *(float4*)&v[q * 4] =
            *(const float4*)(sm + K1_FX + (uint32_t)(row * 68 + quad * 16 + q * 4) * 4);
      uint4 h0, l0, h1, l1;
      split8(v, h0, l0); split8(v + 8, h1, l1);
      const uint32_t off = (uint32_t)(row * 72 + quad * 16) * 2;
      *(uint4*)(sm + K1_AH + off) = h0; *(uint4*)(sm + K1_AH + off + 16) = h1;
      *(uint4*)(sm + K1_AL + off) = l0; *(uint4*)(sm + K1_AL + off + 16) = l1;
    }
    {
      const int row = t >> 1, half = (t & 1) * 32;
      float v[32];
#pragma unroll
      for (int q = 0; q < 8; q++)
        *(float4*)&v[q * 4] =
            *(const float4*)(sm + K1_FW + (uint32_t)(row * 68 + half + q * 4) * 4);
      const uint32_t off = (uint32_t)(row * 72 + half) * 2;
#pragma unroll
      for (int g = 0; g < 4; g++) {
        uint4 hh, ll;
        split8(v + g * 8, hh, ll);
        *(uint4*)(sm + K1_BH + off + g * 16) = hh;
        *(uint4*)(sm + K1_BL + off + g * 16) = ll;
      }
    }
    __syncthreads();
    // ---- prefetch next chunk while MMA runs ----
    if (ch < 3) { K1_LOADF32(ch + 1); CP_COMMIT(); }

    // ---- MMA, 3-term split ----
#pragma unroll
    for (int ks = 0; ks < 64; ks += 16) {
      const uint32_t lrow = (uint32_t)(lane & 15);
      const uint32_t lcol = (uint32_t)(ks + ((lane >> 4) << 3));
      uint32_t ah[2][4], al[2][4];
#pragma unroll
      for (int r = 0; r < 2; r++) {
        uint32_t ra = SB + ((warpM * 32 + r * 16 + lrow) * 72 + lcol) * 2;
        ldsm4(ra + K1_AH, ah[r]);
        ldsm4(ra + K1_AL, al[r]);
      }
      uint32_t bh[8][2], bl[8][2];
#pragma unroll
      for (int q = 0; q < 4; q++) {
        uint32_t rb = SB + ((warpN * 64 + q * 16 + lrow) * 72 + lcol) * 2;
        uint32_t rr[4];
        ldsm4(rb + K1_BH, rr);
        bh[2 * q][0] = rr[0]; bh[2 * q + 1][0] = rr[1];
        bh[2 * q][1] = rr[2]; bh[2 * q + 1][1] = rr[3];
        ldsm4(rb + K1_BL, rr);
        bl[2 * q][0] = rr[0]; bl[2 * q + 1][0] = rr[1];
        bl[2 * q][1] = rr[2]; bl[2 * q + 1][1] = rr[3];
      }
#pragma unroll
      for (int r = 0; r < 2; r++)
#pragma unroll
        for (int f = 0; f < 8; f++) mma16816(c[r][f], ah[r], bh[f][0], bh[f][1]);
#pragma unroll
      for (int r = 0; r < 2; r++)
#pragma unroll
        for (int f = 0; f < 8; f++) mma16816(c[r][f], ah[r], bl[f][0], bl[f][1]);
#pragma unroll
      for (int r = 0; r < 2; r++)
#pragma unroll
        for (int f = 0; f < 8; f++) mma16816(c[r][f], al[r], bh[f][0], bh[f][1]);
    }
    CP_WAIT(0);
    __syncthreads();
  }

  // ---- epilogue: s1/s2 partials + h fp16 stores ----
  const float* as_ = (const float*)(sm + K1_AS);
  float s1p[4], s2p[4];
#pragma unroll
  for (int q = 0; q < 4; q++) { s1p[q] = 0.f; s2p[q] = 0.f; }
#pragma unroll
  for (int r = 0; r < 2; r++)
#pragma unroll
    for (int f = 0; f < 8; f++)
#pragma unroll
      for (int q = 0; q < 4; q++) {
        int col = warpN * 64 + f * 8 + 2 * (lane & 3) + (q & 1);
        int ri = r * 2 + (q >> 1);
        s1p[ri] += c[r][f][q] * as_[col];
        s2p[ri] += c[r][f][q] * as_[256 + col];
      }
#pragma unroll
  for (int o = 1; o < 4; o <<= 1)
#pragma unroll
    for (int ri = 0; ri < 4; ri++) {
      s1p[ri] += __shfl_xor_sync(0xffffffffu, s1p[ri], o);
      s2p[ri] += __shfl_xor_sync(0xffffffffu, s2p[ri], o);
    }
  if ((lane & 3) == 0) {
#pragma unroll
    for (int r = 0; r < 2; r++)
#pragma unroll
      for (int hh = 0; hh < 2; hh++) {
        int rowr = warpM * 32 + r * 16 + (lane >> 2) + hh * 8;
        ((float*)(sm + K1_R1))[warpN * 128 + rowr] = s1p[r * 2 + hh];
        ((float*)(sm + K1_R2))[warpN * 128 + rowr] = s2p[r * 2 + hh];
      }
  }
  // h stores
#pragma unroll
  for (int r = 0; r < 2; r++)
#pragma unroll
    for (int f = 0; f < 8; f++) {
      int row0 = i0 + warpM * 32 + r * 16 + (lane >> 2);
      int col0 = warpN * 64 + f * 8 + 2 * (lane & 3);
#pragma unroll
      for (int hh = 0; hh < 2; hh++) {
        size_t base = (size_t)(row0 + hh * 8) * 256 + col0;
        __half2 ph;
        ph.x = __float2half_rn(c[r][f][hh * 2]);
        ph.y = __float2half_rn(c[r][f][hh * 2 + 1]);
        *(uint32_t*)&g_h[base] = *(uint32_t*)&ph;
      }
    }
  __syncthreads();
  if (t < 128) {
    const float* r1 = (const float*)(sm + K1_R1);
    const float* r2 = (const float*)(sm + K1_R2);
    float v1 = 0.f, v2 = 0.f;
#pragma unroll
    for (int wn = 0; wn < 4; wn++) { v1 += r1[wn * 128 + t]; v2 += r2[wn * 128 + t]; }
    g_s1[i0 + t] = v1;
    g_s2[i0 + t] = v2;
  }
}

// ============================================================================
// K2: attention. 128 CTAs, 512 threads, warp grid 4x4 (warp tile 32x64).
// CTA M=128, N=256, K=2048 in 16 chunks of 128. 2-stage cp.async ring,
// loads issued before MMA; w fp16 on the fly (double-buffered);
// single-term mma; den from rounded w.
// ============================================================================
#define ATB 0                     // 2 stages x [128][264] fp16
#define ATB_STG 67584
#define AT_A 135168               // 2 x [128][136] fp16
#define AT_AST 34816
#define AT_S2 204800              // 2048 f32
#define AT_S1 212992              // 128 f32
#define AT_DB 213504              // 512 f32
#define AT_DEN 215552             // 128 f32
#define AT_SMEM 216064

__global__ __launch_bounds__(512, 1) void k2(float* __restrict__ out) {
  extern __shared__ char sm[];
  const uint32_t SB = smem_u32(sm);
  const int t = threadIdx.x, lane = t & 31, wid = t >> 5;
  const int warpM = wid >> 2, warpN = wid & 3;
  const int b = blockIdx.x >> 4;
  const int i0 = (blockIdx.x & 15) * 128;

  if (t < 128) ((float*)(sm + AT_S1))[t] = g_s1[b * 2048 + i0 + t];
#pragma unroll
  for (int j = t; j < 2048; j += 512)
    ((float*)(sm + AT_S2))[j] = g_s2[b * 2048 + j];
  __syncthreads();

  const float* s2s = (const float*)(sm + AT_S2);
  const int gm = t >> 2, gkh = (t & 3) * 32;   // w-gen: row gm, cols gkh..+31
  const float s1v = ((const float*)(sm + AT_S1))[gm];
  const __half* H = g_h + (size_t)b * 2048 * 256;

  float c[2][8][4];
#pragma unroll
  for (int r = 0; r < 2; r++)
#pragma unroll
    for (int f = 0; f < 8; f++)
#pragma unroll
      for (int q = 0; q < 4; q++) c[r][f][q] = 0.f;
  float dtot = 0.f;

#define GENW(nn, abuf) do {                                                   \
    const int j0_ = (nn) * 128;                                               \
    uint32_t pkk[16];                                                         \
_Pragma("unroll")                                                             \
    for (int g = 0; g < 4; g++) {                                             \
      float4 ea = *(const float4*)&s2s[j0_ + gkh + g * 8];                    \
      float4 eb = *(const float4*)&s2s[j0_ + gkh + g * 8 + 4];                \
      float ev[8] = {ea.x, ea.y, ea.z, ea.w, eb.x, eb.y, eb.z, eb.w};         \
_Pragma("unroll")                                                             \
      for (int q = 0; q < 4; q++) {                                           \
        float e0 = s1v + ev[2 * q];                                           \
        float e1 = s1v + ev[2 * q + 1];                                       \
        e0 = fmaxf(e0, NEG_SLOPE * e0);                                       \
        e1 = fmaxf(e1, NEG_SLOPE * e1);                                       \
        __half w0 = __float2half_rn(__expf(e0));                              \
        __half w1 = __float2half_rn(__expf(e1));                              \
        dtot += __half2float(w0) + __half2float(w1);                          \
        __half2 pp; pp.x = w0; pp.y = w1;                                     \
        pkk[g * 4 + q] = *(uint32_t*)&pp;                                     \
      }                                                                       \
    }                                                                         \
    const uint32_t off_ = (uint32_t)(gm * 136 + gkh) * 2;                     \
_Pragma("unroll")                                                             \
    for (int g = 0; g < 4; g++)                                               \
      *(uint4*)((abuf) + off_ + g * 16) =                                     \
          make_uint4(pkk[4 * g], pkk[4 * g + 1], pkk[4 * g + 2], pkk[4 * g + 3]); \
  } while (0)

#define LOADB(nn, stg) do {                                                   \
    const uint32_t dst_ = SB + ATB + (stg) * ATB_STG;                         \
    const int j0_ = (nn) * 128;                                               \
_Pragma("unroll")                                                             \
    for (int v = 0; v < 8; v++) {                                             \
      int u = v * 512 + t, row = u >> 5, seg = u & 31;                        \
      cpa16(dst_ + (uint32_t)(row * 264 + seg * 8) * 2,                       \
            H + (size_t)(j0_ + row) * 256 + seg * 8);                         \
    }                                                                         \
  } while (0)

  // prologue: chunk 0 data + w
  LOADB(0, 0);
  CP_COMMIT();
  GENW(0, sm + AT_A);
  CP_WAIT(0);
  __syncthreads();

  for (int n = 0; n < 16; n++) {
    const int p = n & 1;
    if (n < 15) { LOADB(n + 1, p ^ 1); CP_COMMIT(); }

    const uint32_t Bst = SB + ATB + p * ATB_STG;
    const uint32_t Ab = SB + AT_A + p * AT_AST;
#pragma unroll
    for (int ks = 0; ks < 128; ks += 16) {
      uint32_t ah[2][4];
#pragma unroll
      for (int r = 0; r < 2; r++)
        ldsm4(Ab + ((warpM * 32 + r * 16 + (lane & 15)) * 136 + ks +
                    ((lane >> 4) << 3)) * 2,
              ah[r]);
      const uint32_t roff =
          (uint32_t)(ks + ((lane >> 3) & 1) * 8 + (lane & 7)) * 264;
      uint32_t bh[8][2];
#pragma unroll
      for (int q = 0; q < 4; q++) {
        uint32_t coff = (uint32_t)(warpN * 64 + q * 16 + ((lane >> 4) << 3));
        uint32_t rr[4];
        ldsm4t(Bst + (roff + coff) * 2, rr);
        bh[2 * q][0] = rr[0]; bh[2 * q][1] = rr[1];
        bh[2 * q + 1][0] = rr[2]; bh[2 * q + 1][1] = rr[3];
      }
#pragma unroll
      for (int r = 0; r < 2; r++)
#pragma unroll
        for (int f = 0; f < 8; f++) mma16816(c[r][f], ah[r], bh[f][0], bh[f][1]);
    }

    if (n < 15) GENW(n + 1, sm + AT_A + (p ^ 1) * AT_AST);
    CP_WAIT(0);
    __syncthreads();
  }

  // ---- denominator + epilogue ----
  ((float*)(sm + AT_DB))[t] = dtot;
  __syncthreads();
  if (t < 128) {
    const float* db = (const float*)(sm + AT_DB);
    ((float*)(sm + AT_DEN))[t] =
        db[4 * t] + db[4 * t + 1] + db[4 * t + 2] + db[4 * t + 3];
  }
  __syncthreads();
  const float* den = (const float*)(sm + AT_DEN);
  float inv[4];
#pragma unroll
  for (int r = 0; r < 2; r++)
#pragma unroll
    for (int hh = 0; hh < 2; hh++)
      inv[r * 2 + hh] =
          1.0f / den[warpM * 32 + r * 16 + (lane >> 2) + hh * 8];

  float* ob = out + ((size_t)b * 2048 + i0) * 256;
#pragma unroll
  for (int r = 0; r < 2; r++)
#pragma unroll
    for (int f = 0; f < 8; f++) {
      int col = warpN * 64 + f * 8 + 2 * (lane & 3);
#pragma unroll
      for (int hh = 0; hh < 2; hh++) {
        int row = warpM * 32 + r * 16 + (lane >> 2) + hh * 8;
        float iv = inv[r * 2 + hh];
        float v0 = c[r][f][hh * 2] * iv;
        float v1 = c[r][f][hh * 2 + 1] * iv;
        v0 = v0 > 0.f ? v0 : expm1f(v0);
        v1 = v1 > 0.f ? v1 : expm1f(v1);
        *(float2*)&ob[(size_t)row * 256 + col] = make_float2(v0, v1);
      }
    }
}

// ============================================================================
extern "C" void kernel_launch(void* const* d_in, const int* in_sizes, int n_in,
                              void* d_out, int out_size) {
  (void)in_sizes; (void)n_in; (void)out_size;
  const float* x = (const float*)d_in[0];
  const float* W = (const float*)d_in[1];
  const float* a = (const float*)d_in[2];
  float* out = (float*)d_out;

  cudaFuncSetAttribute(k1, cudaFuncAttributeMaxDynamicSharedMemorySize, K1_SMEM);
  cudaFuncSetAttribute(k2, cudaFuncAttributeMaxDynamicSharedMemorySize, AT_SMEM);

  k1<<<128, 512, K1_SMEM>>>(x, W, a);
  k2<<<128, 512, AT_SMEM>>>(out);
}